// round 3
// baseline (speedup 1.0000x reference)
#include <cuda_runtime.h>
#include <cuda_bf16.h>

#define MAXN 100000
#define MAXE 1600000
#define C 128

// ---------------- static scratch ----------------
__device__ int   g_cnt[MAXN];
__device__ int   g_fill[MAXN];
__device__ int   g_rowptr[MAXN + 1];
__device__ float g_dinv[MAXN];
__device__ int   g_srcs[MAXE];
__device__ float g_norms[MAXE];
__device__ float g_ax[(size_t)MAXN * C];
__device__ float g_h [(size_t)MAXN * C];
__device__ float g_ah[(size_t)MAXN * C];
__device__ float g_W2[C * C];
__device__ float g_b2[C];

// ---------------- CSR build ----------------
__global__ void init_kernel(int n) {
    int i = blockIdx.x * blockDim.x + threadIdx.x;
    if (i < n) { g_cnt[i] = 0; g_fill[i] = 0; }
}

__global__ void count_kernel(const int* __restrict__ col, int e) {
    int i = blockIdx.x * blockDim.x + threadIdx.x;
    if (i < e) atomicAdd(&g_cnt[col[i]], 1);
}

// single-block exclusive scan over g_cnt -> g_rowptr, also computes dinv
__global__ void scan_kernel(int n) {
    __shared__ int sums[1024];
    int t = threadIdx.x;
    int chunk = (n + 1023) / 1024;
    int start = t * chunk;
    int end = start + chunk; if (end > n) end = n; if (start > n) start = n;
    int s = 0;
    for (int i = start; i < end; i++) s += g_cnt[i];
    sums[t] = s;
    __syncthreads();
    for (int off = 1; off < 1024; off <<= 1) {
        int v = (t >= off) ? sums[t - off] : 0;
        __syncthreads();
        sums[t] += v;
        __syncthreads();
    }
    int run = (t == 0) ? 0 : sums[t - 1];
    for (int i = start; i < end; i++) {
        int c = g_cnt[i];
        g_rowptr[i] = run; run += c;
        g_dinv[i] = rsqrtf((float)(c + 1));   // +1 self loop
    }
    if (t == 1023) g_rowptr[n] = sums[1023];
}

__global__ void scatter_kernel(const int* __restrict__ row,
                               const int* __restrict__ col, int e) {
    int i = blockIdx.x * blockDim.x + threadIdx.x;
    if (i < e) {
        int r = row[i], c = col[i];
        int p = g_rowptr[c] + atomicAdd(&g_fill[c], 1);
        g_srcs[p]  = r;
        g_norms[p] = g_dinv[r] * g_dinv[c];
    }
}

// ---------------- aggregation: warp per target node, MLP=4 unrolled gather ----------
// PHASE 0: src = x (param), dst = g_ax     PHASE 1: src = g_h, dst = g_ah
template <int PHASE>
__global__ void agg128_kernel(const float* __restrict__ xin, int n) {
    int w = (blockIdx.x * blockDim.x + threadIdx.x) >> 5;
    int lane = threadIdx.x & 31;
    if (w >= n) return;
    const float4* __restrict__ s4 = (PHASE == 0) ? (const float4*)xin : (const float4*)g_h;
    float4* __restrict__ d4       = (PHASE == 0) ? (float4*)g_ax      : (float4*)g_ah;

    float di = g_dinv[w];
    float sw = di * di;
    float4 a = s4[(size_t)w * 32 + lane];
    float4 acc = make_float4(a.x * sw, a.y * sw, a.z * sw, a.w * sw);

    int p = g_rowptr[w];
    int end = g_rowptr[w + 1];

    // main: 4 edges per iteration -> 4 independent 512B gathers in flight
    for (; p + 4 <= end; p += 4) {
        int s0 = g_srcs[p + 0], s1 = g_srcs[p + 1];
        int s2 = g_srcs[p + 2], s3 = g_srcs[p + 3];
        float w0 = g_norms[p + 0], w1 = g_norms[p + 1];
        float w2 = g_norms[p + 2], w3 = g_norms[p + 3];
        float4 v0 = s4[(size_t)s0 * 32 + lane];
        float4 v1 = s4[(size_t)s1 * 32 + lane];
        float4 v2 = s4[(size_t)s2 * 32 + lane];
        float4 v3 = s4[(size_t)s3 * 32 + lane];
        acc.x += w0 * v0.x; acc.y += w0 * v0.y; acc.z += w0 * v0.z; acc.w += w0 * v0.w;
        acc.x += w1 * v1.x; acc.y += w1 * v1.y; acc.z += w1 * v1.z; acc.w += w1 * v1.w;
        acc.x += w2 * v2.x; acc.y += w2 * v2.y; acc.z += w2 * v2.z; acc.w += w2 * v2.w;
        acc.x += w3 * v3.x; acc.y += w3 * v3.y; acc.z += w3 * v3.z; acc.w += w3 * v3.w;
    }
    for (; p < end; p++) {
        int s = g_srcs[p]; float wt = g_norms[p];
        float4 v = s4[(size_t)s * 32 + lane];
        acc.x += wt * v.x; acc.y += wt * v.y; acc.z += wt * v.z; acc.w += wt * v.w;
    }
    d4[(size_t)w * 32 + lane] = acc;
}

// ---------------- GEMM: C[n,128] = A[n,128] @ W[128,128] + bias ----------
// MODE 0: A = g_ax, W/bias = W1/b1 params, relu -> g_h
// MODE 1: A = g_ah, W = g_W2, bias = g_b2, split -> out0 (mu), out1 (logstd)
template <int MODE>
__global__ void gemm128_kernel(const float* __restrict__ Wp, const float* __restrict__ bp,
                               float* __restrict__ out0, float* __restrict__ out1, int n) {
    __shared__ float Wt[64 * 128];   // 32 KB K-tile of W
    __shared__ float Xt[64 * 64];    // 16 KB 64 rows x 64 k
    const float* A    = (MODE == 0) ? g_ax : g_ah;
    const float* W    = (MODE == 0) ? Wp : g_W2;
    const float* bias = (MODE == 0) ? bp : g_b2;

    int warp = threadIdx.x >> 5;
    int lane = threadIdx.x & 31;
    int row0 = blockIdx.x * 64;

    float4 acc[8];
#pragma unroll
    for (int r = 0; r < 8; r++) acc[r] = make_float4(0.f, 0.f, 0.f, 0.f);

    const float4* Wt4 = (const float4*)Wt;
    const float4* Xt4 = (const float4*)Xt;

    for (int kt = 0; kt < 2; kt++) {
        for (int i = threadIdx.x; i < 64 * 32; i += 256) {
            ((float4*)Wt)[i] = ((const float4*)W)[(kt * 64 + (i >> 5)) * 32 + (i & 31)];
        }
        for (int i = threadIdx.x; i < 64 * 16; i += 256) {
            int rr = i >> 4, kq = i & 15;
            int r = row0 + rr;
            float4 v = make_float4(0.f, 0.f, 0.f, 0.f);
            if (r < n) v = ((const float4*)A)[(size_t)r * 32 + kt * 16 + kq];
            ((float4*)Xt)[i] = v;
        }
        __syncthreads();

#pragma unroll
        for (int kk = 0; kk < 64; kk += 4) {
            float4 w0 = Wt4[(kk + 0) * 32 + lane];
            float4 w1 = Wt4[(kk + 1) * 32 + lane];
            float4 w2 = Wt4[(kk + 2) * 32 + lane];
            float4 w3 = Wt4[(kk + 3) * 32 + lane];
#pragma unroll
            for (int rr = 0; rr < 8; rr++) {
                float4 xv = Xt4[(warp * 8 + rr) * 16 + (kk >> 2)];   // broadcast
                acc[rr].x += xv.x * w0.x; acc[rr].y += xv.x * w0.y;
                acc[rr].z += xv.x * w0.z; acc[rr].w += xv.x * w0.w;
                acc[rr].x += xv.y * w1.x; acc[rr].y += xv.y * w1.y;
                acc[rr].z += xv.y * w1.z; acc[rr].w += xv.y * w1.w;
                acc[rr].x += xv.z * w2.x; acc[rr].y += xv.z * w2.y;
                acc[rr].z += xv.z * w2.z; acc[rr].w += xv.z * w2.w;
                acc[rr].x += xv.w * w3.x; acc[rr].y += xv.w * w3.y;
                acc[rr].z += xv.w * w3.z; acc[rr].w += xv.w * w3.w;
            }
        }
        __syncthreads();
    }

    float4 b4 = ((const float4*)bias)[lane];
#pragma unroll
    for (int rr = 0; rr < 8; rr++) {
        int row = row0 + warp * 8 + rr;
        if (row >= n) continue;
        float4 v = acc[rr];
        v.x += b4.x; v.y += b4.y; v.z += b4.z; v.w += b4.w;
        if (MODE == 0) {
            v.x = fmaxf(v.x, 0.f); v.y = fmaxf(v.y, 0.f);
            v.z = fmaxf(v.z, 0.f); v.w = fmaxf(v.w, 0.f);
            ((float4*)g_h)[(size_t)row * 32 + lane] = v;
        } else {
            if (lane < 16)
                ((float4*)out0)[(size_t)row * 16 + lane] = v;        // mu
            else
                ((float4*)out1)[(size_t)row * 16 + (lane - 16)] = v; // logstd
        }
    }
}

// pack W2 = [Wmu | Wls], b2 = [bmu | bls]
__global__ void pack_w2_kernel(const float* __restrict__ Wmu, const float* __restrict__ bmu,
                               const float* __restrict__ Wls, const float* __restrict__ bls) {
    int j = threadIdx.x;   // 128
    int k = blockIdx.x;    // 128
    g_W2[k * 128 + j] = (j < 64) ? Wmu[k * 64 + j] : Wls[k * 64 + (j - 64)];
    if (k == 0) g_b2[j] = (j < 64) ? bmu[j] : bls[j - 64];
}

// ---------------- launch ----------------
extern "C" void kernel_launch(void* const* d_in, const int* in_sizes, int n_in,
                              void* d_out, int out_size) {
    const float* x   = (const float*)d_in[0];
    const int*   ei  = (const int*)d_in[1];
    const float* W1  = (const float*)d_in[3];
    const float* b1  = (const float*)d_in[4];
    const float* Wmu = (const float*)d_in[5];
    const float* bmu = (const float*)d_in[6];
    const float* Wls = (const float*)d_in[7];
    const float* bls = (const float*)d_in[8];
    float* out = (float*)d_out;

    int n = in_sizes[0] / C;       // 100000
    int e = in_sizes[1] / 2;       // 1600000
    const int* erow = ei;
    const int* ecol = ei + e;

    float* mu = out;
    float* ls = out + (size_t)n * 64;

    int nb_n = (n + 255) / 256;
    int nb_e = (e + 255) / 256;

    init_kernel<<<nb_n, 256>>>(n);
    count_kernel<<<nb_e, 256>>>(ecol, e);
    scan_kernel<<<1, 1024>>>(n);
    scatter_kernel<<<nb_e, 256>>>(erow, ecol, e);
    pack_w2_kernel<<<128, 128>>>(Wmu, bmu, Wls, bls);

    int agg_blocks = (n + 7) / 8;
    int gemm_blocks = (n + 63) / 64;

    agg128_kernel<0><<<agg_blocks, 256>>>(x, n);
    gemm128_kernel<0><<<gemm_blocks, 256>>>(W1, b1, nullptr, nullptr, n);
    agg128_kernel<1><<<agg_blocks, 256>>>(nullptr, n);
    gemm128_kernel<1><<<gemm_blocks, 256>>>(nullptr, nullptr, mu, ls, n);
}

// round 4
// speedup vs baseline: 1.4487x; 1.4487x over previous
#include <cuda_runtime.h>
#include <cuda_bf16.h>

#define MAXN 100000
#define MAXE 1600000
#define C 128
#define NBMAX 1024   // max scan blocks (n/256 = 391)

// ---------------- static scratch ----------------
__device__ int   g_cnt[MAXN];
__device__ int   g_fill[MAXN];
__device__ int   g_rowptr[MAXN + 1];
__device__ float g_dinv[MAXN];
__device__ int   g_srcs[MAXE];
__device__ int   g_blocksum[NBMAX];
__device__ int   g_blockoff[NBMAX];
__device__ float g_xs[(size_t)MAXN * C];   // dinv-scaled x
__device__ float g_ax[(size_t)MAXN * C];   // agg(x)
__device__ float g_h [(size_t)MAXN * C];   // dinv * relu(agg@W1+b1)  (pre-scaled h)
__device__ float g_ah[(size_t)MAXN * C];   // agg(h)
__device__ float g_W2[C * C];              // [Wmu | Wls]
__device__ float g_b2[C];

// ---------------- CSR build ----------------
__global__ void init_kernel(int n) {
    int i = blockIdx.x * blockDim.x + threadIdx.x;
    if (i < n) { g_cnt[i] = 0; g_fill[i] = 0; }
}

__global__ void count_kernel(const int* __restrict__ col, int e) {
    int i = blockIdx.x * blockDim.x + threadIdx.x;
    if (i < e) atomicAdd(&g_cnt[col[i]], 1);   // no return use -> RED
}

// coalesced 3-phase scan: A) per-block sums  B) scan block sums  C) per-element
__global__ void scanA_kernel(int n) {
    __shared__ int red[256];
    int i = blockIdx.x * 256 + threadIdx.x;
    red[threadIdx.x] = (i < n) ? g_cnt[i] : 0;
    __syncthreads();
    for (int off = 128; off > 0; off >>= 1) {
        if (threadIdx.x < off) red[threadIdx.x] += red[threadIdx.x + off];
        __syncthreads();
    }
    if (threadIdx.x == 0) g_blocksum[blockIdx.x] = red[0];
}

__global__ void scanB_kernel(int nb, int n) {
    __shared__ int s[NBMAX];
    int t = threadIdx.x;
    int v = (t < nb) ? g_blocksum[t] : 0;
    s[t] = v;
    __syncthreads();
    for (int off = 1; off < NBMAX; off <<= 1) {
        int u = (t >= off) ? s[t - off] : 0;
        __syncthreads();
        s[t] += u;
        __syncthreads();
    }
    if (t < nb) g_blockoff[t] = s[t] - v;        // exclusive
    if (t == NBMAX - 1) g_rowptr[n] = s[NBMAX - 1];
}

__global__ void scanC_kernel(int n) {
    __shared__ int s[256];
    int i = blockIdx.x * 256 + threadIdx.x;
    int c = (i < n) ? g_cnt[i] : 0;
    s[threadIdx.x] = c;
    __syncthreads();
    for (int off = 1; off < 256; off <<= 1) {     // inclusive Hillis-Steele
        int u = (threadIdx.x >= off) ? s[threadIdx.x - off] : 0;
        __syncthreads();
        s[threadIdx.x] += u;
        __syncthreads();
    }
    if (i < n) {
        g_rowptr[i] = g_blockoff[blockIdx.x] + s[threadIdx.x] - c;  // exclusive
        g_dinv[i]   = rsqrtf((float)(c + 1));     // +1 self loop
    }
}

__global__ void scatter_kernel(const int* __restrict__ row,
                               const int* __restrict__ col, int e) {
    int i = blockIdx.x * blockDim.x + threadIdx.x;
    if (i < e) {
        int c = col[i];
        int p = g_rowptr[c] + atomicAdd(&g_fill[c], 1);
        g_srcs[p] = row[i];
    }
}

// xs = dinv[node] * x  (streaming, coalesced)
__global__ void scale_kernel(const float* __restrict__ x, int n) {
    int i = blockIdx.x * blockDim.x + threadIdx.x;   // one float4 per thread
    if (i >= n * 32) return;
    float d = g_dinv[i >> 5];
    float4 v = ((const float4*)x)[i];
    v.x *= d; v.y *= d; v.z *= d; v.w *= d;
    ((float4*)g_xs)[i] = v;
}

// ---------------- aggregation: warp/node; dst[c] = dinv[c]*(src[c] + sum src[s]) -----
// PHASE 0: src = g_xs, dst = g_ax     PHASE 1: src = g_h, dst = g_ah
template <int PHASE>
__global__ void agg128_kernel(int n) {
    int w = (blockIdx.x * blockDim.x + threadIdx.x) >> 5;
    int lane = threadIdx.x & 31;
    if (w >= n) return;
    const float4* __restrict__ s4 = (PHASE == 0) ? (const float4*)g_xs : (const float4*)g_h;
    float4* __restrict__ d4       = (PHASE == 0) ? (float4*)g_ax       : (float4*)g_ah;

    float4 acc = s4[(size_t)w * 32 + lane];   // self term (already pre-scaled)

    int p = g_rowptr[w];
    int end = g_rowptr[w + 1];

    for (; p + 4 <= end; p += 4) {
        int s0 = g_srcs[p + 0], s1 = g_srcs[p + 1];
        int s2 = g_srcs[p + 2], s3 = g_srcs[p + 3];
        float4 v0 = s4[(size_t)s0 * 32 + lane];
        float4 v1 = s4[(size_t)s1 * 32 + lane];
        float4 v2 = s4[(size_t)s2 * 32 + lane];
        float4 v3 = s4[(size_t)s3 * 32 + lane];
        acc.x += v0.x + v1.x + v2.x + v3.x;
        acc.y += v0.y + v1.y + v2.y + v3.y;
        acc.z += v0.z + v1.z + v2.z + v3.z;
        acc.w += v0.w + v1.w + v2.w + v3.w;
    }
    for (; p < end; p++) {
        float4 v = s4[(size_t)g_srcs[p] * 32 + lane];
        acc.x += v.x; acc.y += v.y; acc.z += v.z; acc.w += v.w;
    }
    float d = g_dinv[w];
    acc.x *= d; acc.y *= d; acc.z *= d; acc.w *= d;
    d4[(size_t)w * 32 + lane] = acc;
}

// ---------------- GEMM: C[n,128] = A[n,128] @ W[128,128] + bias ----------
// MODE 0: A = g_ax, W/bias = W1/b1 params, out = g_h = dinv[row]*relu(.)
// MODE 1: A = g_ah, W = g_W2, bias = g_b2, split -> out0 (mu), out1 (logstd)
template <int MODE>
__global__ void gemm128_kernel(const float* __restrict__ Wp, const float* __restrict__ bp,
                               float* __restrict__ out0, float* __restrict__ out1, int n) {
    __shared__ float Wt[64 * 128];   // 32 KB K-tile of W
    __shared__ float Xt[64 * 64];    // 16 KB 64 rows x 64 k
    const float* A    = (MODE == 0) ? g_ax : g_ah;
    const float* W    = (MODE == 0) ? Wp : g_W2;
    const float* bias = (MODE == 0) ? bp : g_b2;

    int warp = threadIdx.x >> 5;
    int lane = threadIdx.x & 31;
    int row0 = blockIdx.x * 64;

    float4 acc[8];
#pragma unroll
    for (int r = 0; r < 8; r++) acc[r] = make_float4(0.f, 0.f, 0.f, 0.f);

    const float4* Wt4 = (const float4*)Wt;
    const float4* Xt4 = (const float4*)Xt;

    for (int kt = 0; kt < 2; kt++) {
        for (int i = threadIdx.x; i < 64 * 32; i += 256) {
            ((float4*)Wt)[i] = ((const float4*)W)[(kt * 64 + (i >> 5)) * 32 + (i & 31)];
        }
        for (int i = threadIdx.x; i < 64 * 16; i += 256) {
            int rr = i >> 4, kq = i & 15;
            int r = row0 + rr;
            float4 v = make_float4(0.f, 0.f, 0.f, 0.f);
            if (r < n) v = ((const float4*)A)[(size_t)r * 32 + kt * 16 + kq];
            ((float4*)Xt)[i] = v;
        }
        __syncthreads();

#pragma unroll
        for (int kk = 0; kk < 64; kk += 4) {
            float4 w0 = Wt4[(kk + 0) * 32 + lane];
            float4 w1 = Wt4[(kk + 1) * 32 + lane];
            float4 w2 = Wt4[(kk + 2) * 32 + lane];
            float4 w3 = Wt4[(kk + 3) * 32 + lane];
#pragma unroll
            for (int rr = 0; rr < 8; rr++) {
                float4 xv = Xt4[(warp * 8 + rr) * 16 + (kk >> 2)];   // broadcast
                acc[rr].x += xv.x * w0.x; acc[rr].y += xv.x * w0.y;
                acc[rr].z += xv.x * w0.z; acc[rr].w += xv.x * w0.w;
                acc[rr].x += xv.y * w1.x; acc[rr].y += xv.y * w1.y;
                acc[rr].z += xv.y * w1.z; acc[rr].w += xv.y * w1.w;
                acc[rr].x += xv.z * w2.x; acc[rr].y += xv.z * w2.y;
                acc[rr].z += xv.z * w2.z; acc[rr].w += xv.z * w2.w;
                acc[rr].x += xv.w * w3.x; acc[rr].y += xv.w * w3.y;
                acc[rr].z += xv.w * w3.z; acc[rr].w += xv.w * w3.w;
            }
        }
        __syncthreads();
    }

    float4 b4 = ((const float4*)bias)[lane];
#pragma unroll
    for (int rr = 0; rr < 8; rr++) {
        int row = row0 + warp * 8 + rr;
        if (row >= n) continue;
        float4 v = acc[rr];
        v.x += b4.x; v.y += b4.y; v.z += b4.z; v.w += b4.w;
        if (MODE == 0) {
            float d = g_dinv[row];     // pre-scale h for next aggregation
            v.x = fmaxf(v.x, 0.f) * d; v.y = fmaxf(v.y, 0.f) * d;
            v.z = fmaxf(v.z, 0.f) * d; v.w = fmaxf(v.w, 0.f) * d;
            ((float4*)g_h)[(size_t)row * 32 + lane] = v;
        } else {
            if (lane < 16)
                ((float4*)out0)[(size_t)row * 16 + lane] = v;        // mu
            else
                ((float4*)out1)[(size_t)row * 16 + (lane - 16)] = v; // logstd
        }
    }
}

// pack W2 = [Wmu | Wls], b2 = [bmu | bls]
__global__ void pack_w2_kernel(const float* __restrict__ Wmu, const float* __restrict__ bmu,
                               const float* __restrict__ Wls, const float* __restrict__ bls) {
    int j = threadIdx.x;   // 128
    int k = blockIdx.x;    // 128
    g_W2[k * 128 + j] = (j < 64) ? Wmu[k * 64 + j] : Wls[k * 64 + (j - 64)];
    if (k == 0) g_b2[j] = (j < 64) ? bmu[j] : bls[j - 64];
}

// ---------------- launch ----------------
extern "C" void kernel_launch(void* const* d_in, const int* in_sizes, int n_in,
                              void* d_out, int out_size) {
    const float* x   = (const float*)d_in[0];
    const int*   ei  = (const int*)d_in[1];
    const float* W1  = (const float*)d_in[3];
    const float* b1  = (const float*)d_in[4];
    const float* Wmu = (const float*)d_in[5];
    const float* bmu = (const float*)d_in[6];
    const float* Wls = (const float*)d_in[7];
    const float* bls = (const float*)d_in[8];
    float* out = (float*)d_out;

    int n = in_sizes[0] / C;       // 100000
    int e = in_sizes[1] / 2;       // 1600000
    const int* erow = ei;
    const int* ecol = ei + e;

    float* mu = out;
    float* ls = out + (size_t)n * 64;

    int nb_n = (n + 255) / 256;    // 391
    int nb_e = (e + 255) / 256;

    init_kernel<<<nb_n, 256>>>(n);
    count_kernel<<<nb_e, 256>>>(ecol, e);
    scanA_kernel<<<nb_n, 256>>>(n);
    scanB_kernel<<<1, NBMAX>>>(nb_n, n);
    scanC_kernel<<<nb_n, 256>>>(n);
    scatter_kernel<<<nb_e, 256>>>(erow, ecol, e);
    pack_w2_kernel<<<128, 128>>>(Wmu, bmu, Wls, bls);

    scale_kernel<<<(n * 32 + 255) / 256, 256>>>(x, n);

    int agg_blocks = (n + 7) / 8;
    int gemm_blocks = (n + 63) / 64;

    agg128_kernel<0><<<agg_blocks, 256>>>(n);
    gemm128_kernel<0><<<gemm_blocks, 256>>>(W1, b1, nullptr, nullptr, n);
    agg128_kernel<1><<<agg_blocks, 256>>>(n);
    gemm128_kernel<1><<<gemm_blocks, 256>>>(nullptr, nullptr, mu, ls, n);
}

// round 6
// speedup vs baseline: 1.8316x; 1.2643x over previous
#include <cuda_runtime.h>
#include <cuda_bf16.h>
#include <cstdint>

#define MAXN 100000
#define MAXE 1600000
#define C 128
#define NBMAX 1024
#define KP 136   // padded K row length (bf16 elems): 272B rows -> conflict-free ldmatrix

// ================= static scratch =================
__device__ int   g_cnt[MAXN];
__device__ int   g_fill[MAXN];
__device__ int   g_rowptr[MAXN + 1];
__device__ float g_dinv[MAXN];
__device__ int   g_srcs[MAXE];
__device__ int   g_blocksum[NBMAX];
__device__ int   g_blockoff[NBMAX];
__device__ float g_xs[(size_t)MAXN * C];        // dinv-scaled x (fp32)
__device__ float g_h [(size_t)MAXN * C];        // dinv*relu(layer1) fp32 (gathered by agg1)
__device__ __nv_bfloat16 g_axhi[(size_t)MAXN * C];  // agg(x) bf16 hi
__device__ __nv_bfloat16 g_axlo[(size_t)MAXN * C];  // agg(x) bf16 lo
__device__ __nv_bfloat16 g_ahhi[(size_t)MAXN * C];  // agg(h) bf16 hi
__device__ __nv_bfloat16 g_ahlo[(size_t)MAXN * C];  // agg(h) bf16 lo
__device__ __nv_bfloat16 g_w1hi[C * C], g_w1lo[C * C];  // W1^T  [n][k] bf16 hi/lo
__device__ __nv_bfloat16 g_w2hi[C * C], g_w2lo[C * C];  // [Wmu|Wls]^T
__device__ float g_b2[C];

// ================= MMA helpers (baseline PTX, works on compute_103) =================
__device__ __forceinline__ uint32_t smem_u32(const void* p) {
    uint32_t a;
    asm("{ .reg .u64 t; cvta.to.shared.u64 t, %1; cvt.u32.u64 %0, t; }" : "=r"(a) : "l"(p));
    return a;
}
__device__ __forceinline__ void ldsm_x4(uint32_t* r, uint32_t addr) {
    asm volatile("ldmatrix.sync.aligned.m8n8.x4.shared.b16 {%0,%1,%2,%3}, [%4];"
        : "=r"(r[0]), "=r"(r[1]), "=r"(r[2]), "=r"(r[3]) : "r"(addr));
}
__device__ __forceinline__ void mma16816(float* d, const uint32_t* a, const uint32_t* b) {
    asm volatile("mma.sync.aligned.m16n8k16.row.col.f32.bf16.bf16.f32 "
        "{%0,%1,%2,%3}, {%4,%5,%6,%7}, {%8,%9}, {%0,%1,%2,%3};"
        : "+f"(d[0]), "+f"(d[1]), "+f"(d[2]), "+f"(d[3])
        : "r"(a[0]), "r"(a[1]), "r"(a[2]), "r"(a[3]), "r"(b[0]), "r"(b[1]));
}

// ================= CSR build =================
__global__ void init_kernel(int n) {
    int i = blockIdx.x * blockDim.x + threadIdx.x;
    if (i < n) { g_cnt[i] = 0; g_fill[i] = 0; }
}
__global__ void count_kernel(const int* __restrict__ col, int e) {
    int i = blockIdx.x * blockDim.x + threadIdx.x;
    if (i < e) atomicAdd(&g_cnt[col[i]], 1);
}
__global__ void scanA_kernel(int n) {
    __shared__ int red[256];
    int i = blockIdx.x * 256 + threadIdx.x;
    red[threadIdx.x] = (i < n) ? g_cnt[i] : 0;
    __syncthreads();
    for (int off = 128; off > 0; off >>= 1) {
        if (threadIdx.x < off) red[threadIdx.x] += red[threadIdx.x + off];
        __syncthreads();
    }
    if (threadIdx.x == 0) g_blocksum[blockIdx.x] = red[0];
}
__global__ void scanB_kernel(int nb, int n) {
    __shared__ int s[NBMAX];
    int t = threadIdx.x;
    int v = (t < nb) ? g_blocksum[t] : 0;
    s[t] = v;
    __syncthreads();
    for (int off = 1; off < NBMAX; off <<= 1) {
        int u = (t >= off) ? s[t - off] : 0;
        __syncthreads();
        s[t] += u;
        __syncthreads();
    }
    if (t < nb) g_blockoff[t] = s[t] - v;
    if (t == NBMAX - 1) g_rowptr[n] = s[NBMAX - 1];
}
__global__ void scanC_kernel(int n) {
    __shared__ int s[256];
    int i = blockIdx.x * 256 + threadIdx.x;
    int c = (i < n) ? g_cnt[i] : 0;
    s[threadIdx.x] = c;
    __syncthreads();
    for (int off = 1; off < 256; off <<= 1) {
        int u = (threadIdx.x >= off) ? s[threadIdx.x - off] : 0;
        __syncthreads();
        s[threadIdx.x] += u;
        __syncthreads();
    }
    if (i < n) {
        g_rowptr[i] = g_blockoff[blockIdx.x] + s[threadIdx.x] - c;
        g_dinv[i]   = rsqrtf((float)(c + 1));
    }
}
__global__ void scatter_kernel(const int* __restrict__ row, const int* __restrict__ col, int e) {
    int i = blockIdx.x * blockDim.x + threadIdx.x;
    if (i < e) {
        int c = col[i];
        int p = g_rowptr[c] + atomicAdd(&g_fill[c], 1);
        g_srcs[p] = row[i];
    }
}
__global__ void scale_kernel(const float* __restrict__ x, int n) {
    int i = blockIdx.x * blockDim.x + threadIdx.x;
    if (i >= n * 32) return;
    float d = g_dinv[i >> 5];
    float4 v = ((const float4*)x)[i];
    v.x *= d; v.y *= d; v.z *= d; v.w *= d;
    ((float4*)g_xs)[i] = v;
}

// pack transposed bf16 hi/lo W images: Bt[nn][k] = W[k][nn]
__global__ void packW_kernel(const float* __restrict__ W1,
                             const float* __restrict__ Wmu, const float* __restrict__ bmu,
                             const float* __restrict__ Wls, const float* __restrict__ bls) {
    int k = blockIdx.x;       // 0..127
    int nn = threadIdx.x;     // 0..127
    int layer = blockIdx.y;
    float w;
    if (layer == 0) w = W1[k * 128 + nn];
    else            w = (nn < 64) ? Wmu[k * 64 + nn] : Wls[k * 64 + (nn - 64)];
    __nv_bfloat16 bh = __float2bfloat16_rn(w);
    __nv_bfloat16 bl = __float2bfloat16_rn(w - __bfloat162float(bh));
    if (layer == 0) { g_w1hi[nn * 128 + k] = bh; g_w1lo[nn * 128 + k] = bl; }
    else {
        g_w2hi[nn * 128 + k] = bh; g_w2lo[nn * 128 + k] = bl;
        if (k == 0) g_b2[nn] = (nn < 64) ? bmu[nn] : bls[nn - 64];
    }
}

// ================= aggregation: warp/node, MLP=4; outputs bf16 hi/lo rows ============
__device__ __forceinline__ uint32_t pack_bf2(float a, float b) {
    __nv_bfloat162 t = __halves2bfloat162(__float2bfloat16_rn(a), __float2bfloat16_rn(b));
    return *reinterpret_cast<uint32_t*>(&t);
}
template <int PHASE>
__global__ void agg128_kernel(int n) {
    int w = (blockIdx.x * blockDim.x + threadIdx.x) >> 5;
    int lane = threadIdx.x & 31;
    if (w >= n) return;
    const float4* __restrict__ s4 = (PHASE == 0) ? (const float4*)g_xs : (const float4*)g_h;

    float4 acc = s4[(size_t)w * 32 + lane];
    int p = g_rowptr[w];
    int end = g_rowptr[w + 1];
    for (; p + 4 <= end; p += 4) {
        int s0 = g_srcs[p + 0], s1 = g_srcs[p + 1];
        int s2 = g_srcs[p + 2], s3 = g_srcs[p + 3];
        float4 v0 = s4[(size_t)s0 * 32 + lane];
        float4 v1 = s4[(size_t)s1 * 32 + lane];
        float4 v2 = s4[(size_t)s2 * 32 + lane];
        float4 v3 = s4[(size_t)s3 * 32 + lane];
        acc.x += v0.x + v1.x + v2.x + v3.x;
        acc.y += v0.y + v1.y + v2.y + v3.y;
        acc.z += v0.z + v1.z + v2.z + v3.z;
        acc.w += v0.w + v1.w + v2.w + v3.w;
    }
    for (; p < end; p++) {
        float4 v = s4[(size_t)g_srcs[p] * 32 + lane];
        acc.x += v.x; acc.y += v.y; acc.z += v.z; acc.w += v.w;
    }
    float d = g_dinv[w];
    acc.x *= d; acc.y *= d; acc.z *= d; acc.w *= d;

    uint32_t h0 = pack_bf2(acc.x, acc.y);
    uint32_t h1 = pack_bf2(acc.z, acc.w);
    __nv_bfloat162 hv0 = *reinterpret_cast<__nv_bfloat162*>(&h0);
    __nv_bfloat162 hv1 = *reinterpret_cast<__nv_bfloat162*>(&h1);
    uint32_t l0 = pack_bf2(acc.x - __bfloat162float(hv0.x), acc.y - __bfloat162float(hv0.y));
    uint32_t l1 = pack_bf2(acc.z - __bfloat162float(hv1.x), acc.w - __bfloat162float(hv1.y));

    uint2* dh = (uint2*)((PHASE == 0) ? g_axhi : g_ahhi);
    uint2* dl = (uint2*)((PHASE == 0) ? g_axlo : g_ahlo);
    dh[(size_t)w * 32 + lane] = make_uint2(h0, h1);
    dl[(size_t)w * 32 + lane] = make_uint2(l0, l1);
}

// ================= HMMA GEMM: 128x128 tile, K=128, 3-term bf16 split ==============
// MODE 0: A = agg(x) hi/lo, B = W1 images; epilogue g_h = dinv*relu(D+b1)
// MODE 1: A = agg(h) hi/lo, B = W2 images; split -> mu / logstd (+g_b2)
template <int MODE>
__global__ void __launch_bounds__(256) mma_gemm_kernel(const float* __restrict__ bias1,
                                                       float* __restrict__ out0,
                                                       float* __restrict__ out1, int n) {
    extern __shared__ __align__(16) char smem[];
    __nv_bfloat16* sAh = (__nv_bfloat16*)smem;      // 128 x KP
    __nv_bfloat16* sAl = sAh + 128 * KP;
    __nv_bfloat16* sBh = sAl + 128 * KP;
    __nv_bfloat16* sBl = sBh + 128 * KP;
    int tid = threadIdx.x;
    int lane = tid & 31, wid = tid >> 5;
    int row0 = blockIdx.x * 128;

    // stage tiles: 16B chunks, 128 rows x 16 chunks each
    {
        const uint4* gAh = (const uint4*)((MODE == 0) ? g_axhi : g_ahhi);
        const uint4* gAl = (const uint4*)((MODE == 0) ? g_axlo : g_ahlo);
        const uint4* gBh = (const uint4*)((MODE == 0) ? g_w1hi : g_w2hi);
        const uint4* gBl = (const uint4*)((MODE == 0) ? g_w1lo : g_w2lo);
        for (int i = tid; i < 128 * 16; i += 256) {
            int r = i >> 4, c = i & 15;
            uint4 vh = make_uint4(0, 0, 0, 0), vl = vh;
            if (row0 + r < n) {
                vh = gAh[(size_t)(row0 + r) * 16 + c];
                vl = gAl[(size_t)(row0 + r) * 16 + c];
            }
            *(uint4*)&sAh[r * KP + c * 8] = vh;
            *(uint4*)&sAl[r * KP + c * 8] = vl;
            *(uint4*)&sBh[r * KP + c * 8] = gBh[i];
            *(uint4*)&sBl[r * KP + c * 8] = gBl[i];
        }
    }
    __syncthreads();

    int wm = wid & 3;       // warp row: 32 m each
    int wn = wid >> 2;      // warp col: 64 n each
    float d[2][8][4];
#pragma unroll
    for (int mt = 0; mt < 2; mt++)
#pragma unroll
        for (int nt = 0; nt < 8; nt++)
#pragma unroll
            for (int j = 0; j < 4; j++) d[mt][nt][j] = 0.f;

    uint32_t sbase = smem_u32(smem);
    // ldmatrix thread-address patterns
    int aRow  = wm * 32 + (lane & 15);
    int aKoff = (lane >> 4) << 3;                       // 0 / 8
    int bRow  = wn * 64 + ((lane >> 4) << 3) + (lane & 7);
    int bKoff = ((lane >> 3) & 1) << 3;                 // 0 / 8

#pragma unroll
    for (int term = 0; term < 3; term++) {
        uint32_t Abase = sbase + ((term == 2) ? 1 : 0) * 128 * KP * 2;
        uint32_t Bbase = sbase + 2 * 128 * KP * 2 + ((term == 1) ? 1 : 0) * 128 * KP * 2;
#pragma unroll
        for (int ks = 0; ks < 8; ks++) {
            uint32_t a[2][4];
#pragma unroll
            for (int mt = 0; mt < 2; mt++)
                ldsm_x4(a[mt], Abase + (uint32_t)(((aRow + mt * 16) * KP) + ks * 16 + aKoff) * 2);
            uint32_t b[8][2];
#pragma unroll
            for (int nt2 = 0; nt2 < 4; nt2++) {
                uint32_t r4[4];
                ldsm_x4(r4, Bbase + (uint32_t)(((bRow + nt2 * 16) * KP) + ks * 16 + bKoff) * 2);
                b[nt2 * 2 + 0][0] = r4[0]; b[nt2 * 2 + 0][1] = r4[1];
                b[nt2 * 2 + 1][0] = r4[2]; b[nt2 * 2 + 1][1] = r4[3];
            }
#pragma unroll
            for (int mt = 0; mt < 2; mt++)
#pragma unroll
                for (int nt = 0; nt < 8; nt++)
                    mma16816(d[mt][nt], a[mt], b[nt]);
        }
    }

    // epilogue
    const float* bias = (MODE == 0) ? bias1 : g_b2;
    int quad = lane >> 2, tq = lane & 3;
#pragma unroll
    for (int mt = 0; mt < 2; mt++) {
        int ra = row0 + wm * 32 + mt * 16 + quad;
        int rb = ra + 8;
        float da = 0.f, db = 0.f;
        if (MODE == 0) {
            if (ra < n) da = g_dinv[ra];
            if (rb < n) db = g_dinv[rb];
        }
#pragma unroll
        for (int nt = 0; nt < 8; nt++) {
            int c = wn * 64 + nt * 8 + tq * 2;
            float b0 = bias[c], b1 = bias[c + 1];
            if (MODE == 0) {
                if (ra < n) {
                    float2 v;
                    v.x = fmaxf(d[mt][nt][0] + b0, 0.f) * da;
                    v.y = fmaxf(d[mt][nt][1] + b1, 0.f) * da;
                    *(float2*)&g_h[(size_t)ra * 128 + c] = v;
                }
                if (rb < n) {
                    float2 v;
                    v.x = fmaxf(d[mt][nt][2] + b0, 0.f) * db;
                    v.y = fmaxf(d[mt][nt][3] + b1, 0.f) * db;
                    *(float2*)&g_h[(size_t)rb * 128 + c] = v;
                }
            } else {
                float* dst = (c < 64) ? out0 : out1;
                int cc = (c < 64) ? c : c - 64;
                if (ra < n) {
                    float2 v = make_float2(d[mt][nt][0] + b0, d[mt][nt][1] + b1);
                    *(float2*)&dst[(size_t)ra * 64 + cc] = v;
                }
                if (rb < n) {
                    float2 v = make_float2(d[mt][nt][2] + b0, d[mt][nt][3] + b1);
                    *(float2*)&dst[(size_t)rb * 64 + cc] = v;
                }
            }
        }
    }
}

// ================= launch =================
#define SM_TOTAL (4 * 128 * KP * 2)

extern "C" void kernel_launch(void* const* d_in, const int* in_sizes, int n_in,
                              void* d_out, int out_size) {
    const float* x   = (const float*)d_in[0];
    const int*   ei  = (const int*)d_in[1];
    const float* W1  = (const float*)d_in[3];
    const float* b1  = (const float*)d_in[4];
    const float* Wmu = (const float*)d_in[5];
    const float* bmu = (const float*)d_in[6];
    const float* Wls = (const float*)d_in[7];
    const float* bls = (const float*)d_in[8];
    float* out = (float*)d_out;

    int n = in_sizes[0] / C;
    int e = in_sizes[1] / 2;
    const int* erow = ei;
    const int* ecol = ei + e;

    float* mu = out;
    float* ls = out + (size_t)n * 64;

    int nb_n = (n + 255) / 256;
    int nb_e = (e + 255) / 256;

    cudaFuncSetAttribute(mma_gemm_kernel<0>, cudaFuncAttributeMaxDynamicSharedMemorySize, SM_TOTAL);
    cudaFuncSetAttribute(mma_gemm_kernel<1>, cudaFuncAttributeMaxDynamicSharedMemorySize, SM_TOTAL);

    init_kernel<<<nb_n, 256>>>(n);
    count_kernel<<<nb_e, 256>>>(ecol, e);
    scanA_kernel<<<nb_n, 256>>>(n);
    scanB_kernel<<<1, NBMAX>>>(nb_n, n);
    scanC_kernel<<<nb_n, 256>>>(n);
    scatter_kernel<<<nb_e, 256>>>(erow, ecol, e);
    dim3 pw(128, 2);
    packW_kernel<<<pw, 128>>>(W1, Wmu, bmu, Wls, bls);
    scale_kernel<<<(n * 32 + 255) / 256, 256>>>(x, n);

    int agg_blocks = (n + 7) / 8;
    int gemm_blocks = (n + 127) / 128;

    agg128_kernel<0><<<agg_blocks, 256>>>(n);
    mma_gemm_kernel<0><<<gemm_blocks, 256, SM_TOTAL>>>(b1, nullptr, nullptr, n);
    agg128_kernel<1><<<agg_blocks, 256>>>(n);
    mma_gemm_kernel<1><<<gemm_blocks, 256, SM_TOTAL>>>(nullptr, mu, ls, n);
}

// round 7
// speedup vs baseline: 1.8921x; 1.0330x over previous
#include <cuda_runtime.h>
#include <cuda_bf16.h>
#include <cstdint>

#define MAXN 100000
#define MAXE 1600000
#define C 128
#define NBMAX 1024
#define KP 136   // padded K row length (bf16 elems): 272B rows -> conflict-free ldmatrix

// ================= static scratch =================
__device__ int   g_cnt[MAXN];
__device__ int   g_rowptr[MAXN + 1];
__device__ float g_dinv[MAXN];
__device__ int   g_srcs[MAXE];
__device__ int   g_blocksum[NBMAX];
__device__ int   g_blockoff[NBMAX];
__device__ float g_h [(size_t)MAXN * C];        // dinv*relu(layer1) fp32 (gathered by agg1)
__device__ __nv_bfloat16 g_axhi[(size_t)MAXN * C];  // agg(x) bf16 hi
__device__ __nv_bfloat16 g_axlo[(size_t)MAXN * C];  // agg(x) bf16 lo
__device__ __nv_bfloat16 g_ahhi[(size_t)MAXN * C];  // agg(h) bf16 hi
__device__ __nv_bfloat16 g_ahlo[(size_t)MAXN * C];  // agg(h) bf16 lo
__device__ __nv_bfloat16 g_w1hi[C * C], g_w1lo[C * C];  // W1^T  [n][k] bf16 hi/lo
__device__ __nv_bfloat16 g_w2hi[C * C], g_w2lo[C * C];  // [Wmu|Wls]^T
__device__ float g_b2[C];

// ================= MMA helpers (baseline PTX) =================
__device__ __forceinline__ uint32_t smem_u32(const void* p) {
    uint32_t a;
    asm("{ .reg .u64 t; cvta.to.shared.u64 t, %1; cvt.u32.u64 %0, t; }" : "=r"(a) : "l"(p));
    return a;
}
__device__ __forceinline__ void ldsm_x4(uint32_t* r, uint32_t addr) {
    asm volatile("ldmatrix.sync.aligned.m8n8.x4.shared.b16 {%0,%1,%2,%3}, [%4];"
        : "=r"(r[0]), "=r"(r[1]), "=r"(r[2]), "=r"(r[3]) : "r"(addr));
}
__device__ __forceinline__ void mma16816(float* d, const uint32_t* a, const uint32_t* b) {
    asm volatile("mma.sync.aligned.m16n8k16.row.col.f32.bf16.bf16.f32 "
        "{%0,%1,%2,%3}, {%4,%5,%6,%7}, {%8,%9}, {%0,%1,%2,%3};"
        : "+f"(d[0]), "+f"(d[1]), "+f"(d[2]), "+f"(d[3])
        : "r"(a[0]), "r"(a[1]), "r"(a[2]), "r"(a[3]), "r"(b[0]), "r"(b[1]));
}

// ================= CSR build =================
__global__ void init_kernel(int n) {
    int i = blockIdx.x * blockDim.x + threadIdx.x;
    if (i < n) g_cnt[i] = 0;
}
__global__ void count_kernel(const int* __restrict__ col, int e) {
    int i = blockIdx.x * blockDim.x + threadIdx.x;
    if (i < e) atomicAdd(&g_cnt[col[i]], 1);
}
__global__ void scanA_kernel(int n) {
    __shared__ int red[256];
    int i = blockIdx.x * 256 + threadIdx.x;
    red[threadIdx.x] = (i < n) ? g_cnt[i] : 0;
    __syncthreads();
    for (int off = 128; off > 0; off >>= 1) {
        if (threadIdx.x < off) red[threadIdx.x] += red[threadIdx.x + off];
        __syncthreads();
    }
    if (threadIdx.x == 0) g_blocksum[blockIdx.x] = red[0];
}
__global__ void scanB_kernel(int nb, int n) {
    __shared__ int s[NBMAX];
    int t = threadIdx.x;
    int v = (t < nb) ? g_blocksum[t] : 0;
    s[t] = v;
    __syncthreads();
    for (int off = 1; off < NBMAX; off <<= 1) {
        int u = (t >= off) ? s[t - off] : 0;
        __syncthreads();
        s[t] += u;
        __syncthreads();
    }
    if (t < nb) g_blockoff[t] = s[t] - v;
    if (t == NBMAX - 1) g_rowptr[n] = s[NBMAX - 1];
}
__global__ void scanC_kernel(int n) {
    __shared__ int s[256];
    int i = blockIdx.x * 256 + threadIdx.x;
    int c = (i < n) ? g_cnt[i] : 0;
    s[threadIdx.x] = c;
    __syncthreads();
    for (int off = 1; off < 256; off <<= 1) {
        int u = (threadIdx.x >= off) ? s[threadIdx.x - off] : 0;
        __syncthreads();
        s[threadIdx.x] += u;
        __syncthreads();
    }
    if (i < n) {
        g_rowptr[i] = g_blockoff[blockIdx.x] + s[threadIdx.x] - c;
        g_dinv[i]   = rsqrtf((float)(c + 1));
    }
}
// consumes g_cnt destructively (fill from the end of each segment)
__global__ void scatter_kernel(const int* __restrict__ row, const int* __restrict__ col, int e) {
    int i = blockIdx.x * blockDim.x + threadIdx.x;
    if (i < e) {
        int c = col[i];
        int p = g_rowptr[c] + atomicSub(&g_cnt[c], 1) - 1;
        g_srcs[p] = row[i];
    }
}

// pack transposed bf16 hi/lo W images: Bt[nn][k] = W[k][nn]
__global__ void packW_kernel(const float* __restrict__ W1,
                             const float* __restrict__ Wmu, const float* __restrict__ bmu,
                             const float* __restrict__ Wls, const float* __restrict__ bls) {
    int k = blockIdx.x;
    int nn = threadIdx.x;
    int layer = blockIdx.y;
    float w;
    if (layer == 0) w = W1[k * 128 + nn];
    else            w = (nn < 64) ? Wmu[k * 64 + nn] : Wls[k * 64 + (nn - 64)];
    __nv_bfloat16 bh = __float2bfloat16_rn(w);
    __nv_bfloat16 bl = __float2bfloat16_rn(w - __bfloat162float(bh));
    if (layer == 0) { g_w1hi[nn * 128 + k] = bh; g_w1lo[nn * 128 + k] = bl; }
    else {
        g_w2hi[nn * 128 + k] = bh; g_w2lo[nn * 128 + k] = bl;
        if (k == 0) g_b2[nn] = (nn < 64) ? bmu[nn] : bls[nn - 64];
    }
}

// ================= aggregation: warp/node, MLP=8; outputs bf16 hi/lo rows ============
// PHASE 0: src = x (fp32 input, weighted by dinv[s] per edge)
// PHASE 1: src = g_h (already pre-scaled by dinv in gemm0 epilogue, pure add)
__device__ __forceinline__ uint32_t pack_bf2(float a, float b) {
    __nv_bfloat162 t = __halves2bfloat162(__float2bfloat16_rn(a), __float2bfloat16_rn(b));
    return *reinterpret_cast<uint32_t*>(&t);
}
template <int PHASE>
__global__ void agg128_kernel(const float* __restrict__ xin, int n) {
    int w = (blockIdx.x * blockDim.x + threadIdx.x) >> 5;
    int lane = threadIdx.x & 31;
    if (w >= n) return;
    const float4* __restrict__ s4 = (PHASE == 0) ? (const float4*)xin : (const float4*)g_h;

    float dw = g_dinv[w];
    float4 acc = s4[(size_t)w * 32 + lane];
    if (PHASE == 0) { acc.x *= dw; acc.y *= dw; acc.z *= dw; acc.w *= dw; }

    int p = g_rowptr[w];
    int end = g_rowptr[w + 1];

    for (; p + 8 <= end; p += 8) {
        int s[8]; float wt[8];
#pragma unroll
        for (int j = 0; j < 8; j++) s[j] = g_srcs[p + j];
#pragma unroll
        for (int j = 0; j < 8; j++) wt[j] = (PHASE == 0) ? g_dinv[s[j]] : 1.f;
        float4 v[8];
#pragma unroll
        for (int j = 0; j < 8; j++) v[j] = s4[(size_t)s[j] * 32 + lane];
#pragma unroll
        for (int j = 0; j < 8; j++) {
            if (PHASE == 0) {
                acc.x += wt[j] * v[j].x; acc.y += wt[j] * v[j].y;
                acc.z += wt[j] * v[j].z; acc.w += wt[j] * v[j].w;
            } else {
                acc.x += v[j].x; acc.y += v[j].y; acc.z += v[j].z; acc.w += v[j].w;
            }
        }
    }
    for (; p + 4 <= end; p += 4) {
        int s[4]; float wt[4];
#pragma unroll
        for (int j = 0; j < 4; j++) s[j] = g_srcs[p + j];
#pragma unroll
        for (int j = 0; j < 4; j++) wt[j] = (PHASE == 0) ? g_dinv[s[j]] : 1.f;
        float4 v[4];
#pragma unroll
        for (int j = 0; j < 4; j++) v[j] = s4[(size_t)s[j] * 32 + lane];
#pragma unroll
        for (int j = 0; j < 4; j++) {
            if (PHASE == 0) {
                acc.x += wt[j] * v[j].x; acc.y += wt[j] * v[j].y;
                acc.z += wt[j] * v[j].z; acc.w += wt[j] * v[j].w;
            } else {
                acc.x += v[j].x; acc.y += v[j].y; acc.z += v[j].z; acc.w += v[j].w;
            }
        }
    }
    for (; p < end; p++) {
        int s = g_srcs[p];
        float wt = (PHASE == 0) ? g_dinv[s] : 1.f;
        float4 v = s4[(size_t)s * 32 + lane];
        if (PHASE == 0) {
            acc.x += wt * v.x; acc.y += wt * v.y; acc.z += wt * v.z; acc.w += wt * v.w;
        } else {
            acc.x += v.x; acc.y += v.y; acc.z += v.z; acc.w += v.w;
        }
    }
    acc.x *= dw; acc.y *= dw; acc.z *= dw; acc.w *= dw;

    uint32_t h0 = pack_bf2(acc.x, acc.y);
    uint32_t h1 = pack_bf2(acc.z, acc.w);
    __nv_bfloat162 hv0 = *reinterpret_cast<__nv_bfloat162*>(&h0);
    __nv_bfloat162 hv1 = *reinterpret_cast<__nv_bfloat162*>(&h1);
    uint32_t l0 = pack_bf2(acc.x - __bfloat162float(hv0.x), acc.y - __bfloat162float(hv0.y));
    uint32_t l1 = pack_bf2(acc.z - __bfloat162float(hv1.x), acc.w - __bfloat162float(hv1.y));

    uint2* dh = (uint2*)((PHASE == 0) ? g_axhi : g_ahhi);
    uint2* dl = (uint2*)((PHASE == 0) ? g_axlo : g_ahlo);
    dh[(size_t)w * 32 + lane] = make_uint2(h0, h1);
    dl[(size_t)w * 32 + lane] = make_uint2(l0, l1);
}

// ================= HMMA GEMM: 128x128 tile, K=128, 3-term bf16 split ==============
template <int MODE>
__global__ void __launch_bounds__(256) mma_gemm_kernel(const float* __restrict__ bias1,
                                                       float* __restrict__ out0,
                                                       float* __restrict__ out1, int n) {
    extern __shared__ __align__(16) char smem[];
    __nv_bfloat16* sAh = (__nv_bfloat16*)smem;      // 128 x KP
    __nv_bfloat16* sAl = sAh + 128 * KP;
    __nv_bfloat16* sBh = sAl + 128 * KP;
    __nv_bfloat16* sBl = sBh + 128 * KP;
    int tid = threadIdx.x;
    int lane = tid & 31, wid = tid >> 5;
    int row0 = blockIdx.x * 128;

    {
        const uint4* gAh = (const uint4*)((MODE == 0) ? g_axhi : g_ahhi);
        const uint4* gAl = (const uint4*)((MODE == 0) ? g_axlo : g_ahlo);
        const uint4* gBh = (const uint4*)((MODE == 0) ? g_w1hi : g_w2hi);
        const uint4* gBl = (const uint4*)((MODE == 0) ? g_w1lo : g_w2lo);
        for (int i = tid; i < 128 * 16; i += 256) {
            int r = i >> 4, c = i & 15;
            uint4 vh = make_uint4(0, 0, 0, 0), vl = vh;
            if (row0 + r < n) {
                vh = gAh[(size_t)(row0 + r) * 16 + c];
                vl = gAl[(size_t)(row0 + r) * 16 + c];
            }
            *(uint4*)&sAh[r * KP + c * 8] = vh;
            *(uint4*)&sAl[r * KP + c * 8] = vl;
            *(uint4*)&sBh[r * KP + c * 8] = gBh[i];
            *(uint4*)&sBl[r * KP + c * 8] = gBl[i];
        }
    }
    __syncthreads();

    int wm = wid & 3;
    int wn = wid >> 2;
    float d[2][8][4];
#pragma unroll
    for (int mt = 0; mt < 2; mt++)
#pragma unroll
        for (int nt = 0; nt < 8; nt++)
#pragma unroll
            for (int j = 0; j < 4; j++) d[mt][nt][j] = 0.f;

    uint32_t sbase = smem_u32(smem);
    int aRow  = wm * 32 + (lane & 15);
    int aKoff = (lane >> 4) << 3;
    int bRow  = wn * 64 + ((lane >> 4) << 3) + (lane & 7);
    int bKoff = ((lane >> 3) & 1) << 3;

#pragma unroll
    for (int term = 0; term < 3; term++) {
        uint32_t Abase = sbase + ((term == 2) ? 1 : 0) * 128 * KP * 2;
        uint32_t Bbase = sbase + 2 * 128 * KP * 2 + ((term == 1) ? 1 : 0) * 128 * KP * 2;
#pragma unroll
        for (int ks = 0; ks < 8; ks++) {
            uint32_t a[2][4];
#pragma unroll
            for (int mt = 0; mt < 2; mt++)
                ldsm_x4(a[mt], Abase + (uint32_t)(((aRow + mt * 16) * KP) + ks * 16 + aKoff) * 2);
            uint32_t b[8][2];
#pragma unroll
            for (int nt2 = 0; nt2 < 4; nt2++) {
                uint32_t r4[4];
                ldsm_x4(r4, Bbase + (uint32_t)(((bRow + nt2 * 16) * KP) + ks * 16 + bKoff) * 2);
                b[nt2 * 2 + 0][0] = r4[0]; b[nt2 * 2 + 0][1] = r4[1];
                b[nt2 * 2 + 1][0] = r4[2]; b[nt2 * 2 + 1][1] = r4[3];
            }
#pragma unroll
            for (int mt = 0; mt < 2; mt++)
#pragma unroll
                for (int nt = 0; nt < 8; nt++)
                    mma16816(d[mt][nt], a[mt], b[nt]);
        }
    }

    const float* bias = (MODE == 0) ? bias1 : g_b2;
    int quad = lane >> 2, tq = lane & 3;
#pragma unroll
    for (int mt = 0; mt < 2; mt++) {
        int ra = row0 + wm * 32 + mt * 16 + quad;
        int rb = ra + 8;
        float da = 0.f, db = 0.f;
        if (MODE == 0) {
            if (ra < n) da = g_dinv[ra];
            if (rb < n) db = g_dinv[rb];
        }
#pragma unroll
        for (int nt = 0; nt < 8; nt++) {
            int c = wn * 64 + nt * 8 + tq * 2;
            float b0 = bias[c], b1 = bias[c + 1];
            if (MODE == 0) {
                if (ra < n) {
                    float2 v;
                    v.x = fmaxf(d[mt][nt][0] + b0, 0.f) * da;
                    v.y = fmaxf(d[mt][nt][1] + b1, 0.f) * da;
                    *(float2*)&g_h[(size_t)ra * 128 + c] = v;
                }
                if (rb < n) {
                    float2 v;
                    v.x = fmaxf(d[mt][nt][2] + b0, 0.f) * db;
                    v.y = fmaxf(d[mt][nt][3] + b1, 0.f) * db;
                    *(float2*)&g_h[(size_t)rb * 128 + c] = v;
                }
            } else {
                float* dst = (c < 64) ? out0 : out1;
                int cc = (c < 64) ? c : c - 64;
                if (ra < n) {
                    float2 v = make_float2(d[mt][nt][0] + b0, d[mt][nt][1] + b1);
                    *(float2*)&dst[(size_t)ra * 64 + cc] = v;
                }
                if (rb < n) {
                    float2 v = make_float2(d[mt][nt][2] + b0, d[mt][nt][3] + b1);
                    *(float2*)&dst[(size_t)rb * 64 + cc] = v;
                }
            }
        }
    }
}

// ================= launch =================
#define SM_TOTAL (4 * 128 * KP * 2)

extern "C" void kernel_launch(void* const* d_in, const int* in_sizes, int n_in,
                              void* d_out, int out_size) {
    const float* x   = (const float*)d_in[0];
    const int*   ei  = (const int*)d_in[1];
    const float* W1  = (const float*)d_in[3];
    const float* b1  = (const float*)d_in[4];
    const float* Wmu = (const float*)d_in[5];
    const float* bmu = (const float*)d_in[6];
    const float* Wls = (const float*)d_in[7];
    const float* bls = (const float*)d_in[8];
    float* out = (float*)d_out;

    int n = in_sizes[0] / C;
    int e = in_sizes[1] / 2;
    const int* erow = ei;
    const int* ecol = ei + e;

    float* mu = out;
    float* ls = out + (size_t)n * 64;

    int nb_n = (n + 255) / 256;
    int nb_e = (e + 255) / 256;

    cudaFuncSetAttribute(mma_gemm_kernel<0>, cudaFuncAttributeMaxDynamicSharedMemorySize, SM_TOTAL);
    cudaFuncSetAttribute(mma_gemm_kernel<1>, cudaFuncAttributeMaxDynamicSharedMemorySize, SM_TOTAL);

    init_kernel<<<nb_n, 256>>>(n);
    count_kernel<<<nb_e, 256>>>(ecol, e);
    scanA_kernel<<<nb_n, 256>>>(n);
    scanB_kernel<<<1, NBMAX>>>(nb_n, n);
    scanC_kernel<<<nb_n, 256>>>(n);
    scatter_kernel<<<nb_e, 256>>>(erow, ecol, e);
    dim3 pw(128, 2);
    packW_kernel<<<pw, 128>>>(W1, Wmu, bmu, Wls, bls);

    int agg_blocks = (n + 7) / 8;
    int gemm_blocks = (n + 127) / 128;

    agg128_kernel<0><<<agg_blocks, 256>>>(x, n);
    mma_gemm_kernel<0><<<gemm_blocks, 256, SM_TOTAL>>>(b1, nullptr, nullptr, n);
    agg128_kernel<1><<<agg_blocks, 256>>>(nullptr, n);
    mma_gemm_kernel<1><<<gemm_blocks, 256, SM_TOTAL>>>(nullptr, mu, ls, n);
}